// round 1
// baseline (speedup 1.0000x reference)
#include <cuda_runtime.h>
#include <math.h>
#include <stdint.h>

#define TT 4
#define NN 20000
#define EE 320000
#define RR 2
#define DD 64
#define HH 4
#define CC 64
#define HC 256   // H*C

// ----------------- scratch (static device globals; no allocation) -----------------
__device__ float g_hs[NN * HC];
__device__ float g_als[NN * HH];
__device__ float g_ald[NN * HH];
__device__ float g_num[NN * HC];
__device__ float g_denom[NN * HH];
__device__ float g_intra[TT * NN * RR * CC];
__device__ float g_ssum[TT * RR];
__device__ float g_beta[TT * RR];
__device__ float g_inter[TT * NN * CC];
__device__ float g_xg[TT * NN * HC];
__device__ float g_gates[NN * HC];
__device__ float g_lh[NN * CC];
__device__ float g_lc[NN * CC];
__device__ float g_feats[NN * TT * CC];
__device__ float g_WihT[DD * HC];
__device__ float g_WhhT[DD * HC];
__device__ float g_biassum[HC];
__device__ float g_folds[RR * DD * HH];
__device__ float g_foldd[RR * DD * HH];

// ----------------- small helpers -----------------
__device__ __forceinline__ float sigmoidf_(float x) { return 1.0f / (1.0f + __expf(-x)); }

__device__ __forceinline__ void red_add_v4(float* p, float a, float b, float c, float d) {
    asm volatile("red.global.add.v4.f32 [%0], {%1,%2,%3,%4};"
                 :: "l"(p), "f"(a), "f"(b), "f"(c), "f"(d) : "memory");
}

// ----------------- generic zeroing -----------------
__global__ void zero2_kernel(float* a, int na, float* b, int nb) {
    int i = blockIdx.x * blockDim.x + threadIdx.x;
    int st = gridDim.x * blockDim.x;
    for (int j = i; j < na; j += st) a[j] = 0.f;
    for (int j = i; j < nb; j += st) b[j] = 0.f;
}

// ----------------- prep kernels -----------------
// folds[r][k][h] = sum_c W_src[r][k][h*64+c] * att_src[r][h][c]   (same for dst)
__global__ void fold_att_kernel(const float* __restrict__ Wsrc, const float* __restrict__ Wdst,
                                const float* __restrict__ as_, const float* __restrict__ ad_,
                                float* __restrict__ fs, float* __restrict__ fd) {
    int idx = blockIdx.x * blockDim.x + threadIdx.x;
    if (idx >= RR * DD * HH) return;
    int r = idx / (DD * HH);
    int k = (idx / HH) % DD;
    int h = idx % HH;
    float accs = 0.f, accd = 0.f;
    for (int c = 0; c < CC; ++c) {
        accs += Wsrc[((size_t)(r * DD + k)) * HC + h * CC + c] * as_[(r * HH + h) * CC + c];
        accd += Wdst[((size_t)(r * DD + k)) * HC + h * CC + c] * ad_[(r * HH + h) * CC + c];
    }
    fs[idx] = accs;
    fd[idx] = accd;
}

// WT[c][r] = W[r][c]   (W: rows x cols)
__global__ void transpose_kernel(const float* __restrict__ W, float* __restrict__ WT,
                                 int rows, int cols) {
    int idx = blockIdx.x * blockDim.x + threadIdx.x;
    if (idx >= rows * cols) return;
    int r = idx / cols, c = idx % cols;
    WT[c * rows + r] = W[idx];
}

__global__ void bias_sum_kernel(const float* __restrict__ b1, const float* __restrict__ b2,
                                float* __restrict__ out) {
    int i = threadIdx.x;
    if (i < HC) out[i] = b1[i] + b2[i];
}

// ----------------- K=64 SGEMM: C[M,NC] = A[M,64] @ B[64,NC] (+add +bias) -----------------
__global__ __launch_bounds__(256) void gemm_k64(
    const float* __restrict__ A, const float* __restrict__ B, float* __restrict__ C,
    int M, int NC, const float* __restrict__ addsrc, const float* __restrict__ bias) {
    __shared__ float As[64][65];
    __shared__ float Bs[64][65];
    int tid = threadIdx.x;
    int row0 = blockIdx.y * 64;
    int col0 = blockIdx.x * 64;
#pragma unroll
    for (int i = 0; i < 16; ++i) {
        int idx = tid + i * 256;
        int r = idx >> 6, c = idx & 63;
        As[r][c] = (row0 + r < M) ? A[(size_t)(row0 + r) * 64 + c] : 0.f;
        Bs[r][c] = (col0 + c < NC) ? B[(size_t)r * NC + col0 + c] : 0.f;
    }
    __syncthreads();
    int tx = tid & 15, ty = tid >> 4;
    float acc[4][4] = {};
#pragma unroll 8
    for (int k = 0; k < 64; ++k) {
        float a0 = As[ty * 4 + 0][k], a1 = As[ty * 4 + 1][k];
        float a2 = As[ty * 4 + 2][k], a3 = As[ty * 4 + 3][k];
        float b0 = Bs[k][tx * 4 + 0], b1 = Bs[k][tx * 4 + 1];
        float b2 = Bs[k][tx * 4 + 2], b3 = Bs[k][tx * 4 + 3];
        acc[0][0] += a0 * b0; acc[0][1] += a0 * b1; acc[0][2] += a0 * b2; acc[0][3] += a0 * b3;
        acc[1][0] += a1 * b0; acc[1][1] += a1 * b1; acc[1][2] += a1 * b2; acc[1][3] += a1 * b3;
        acc[2][0] += a2 * b0; acc[2][1] += a2 * b1; acc[2][2] += a2 * b2; acc[2][3] += a2 * b3;
        acc[3][0] += a3 * b0; acc[3][1] += a3 * b1; acc[3][2] += a3 * b2; acc[3][3] += a3 * b3;
    }
#pragma unroll
    for (int m = 0; m < 4; ++m) {
#pragma unroll
        for (int n = 0; n < 4; ++n) {
            int gr = row0 + ty * 4 + m, gc = col0 + tx * 4 + n;
            if (gr < M && gc < NC) {
                float v = acc[m][n];
                if (addsrc) v += addsrc[(size_t)gr * NC + gc];
                if (bias) v += bias[gc];
                C[(size_t)gr * NC + gc] = v;
            }
        }
    }
}

// ----------------- attention-score projections (linear fold) -----------------
__global__ void als_kernel(const float* __restrict__ x, const float* __restrict__ fs,
                           const float* __restrict__ fd, float* __restrict__ als,
                           float* __restrict__ ald) {
    int idx = blockIdx.x * blockDim.x + threadIdx.x;
    if (idx >= NN * HH) return;
    int n = idx >> 2, h = idx & 3;
    const float* xr = x + (size_t)n * DD;
    float a = 0.f, b = 0.f;
#pragma unroll 8
    for (int k = 0; k < DD; ++k) {
        float xv = __ldg(xr + k);
        a += xv * fs[k * HH + h];
        b += xv * fd[k * HH + h];
    }
    als[idx] = a;
    ald[idx] = b;
}

// ----------------- edge scatter: warp per edge -----------------
__global__ __launch_bounds__(256) void gat_edge_kernel(
    const int* __restrict__ ei, const float* __restrict__ hs,
    const float* __restrict__ als, const float* __restrict__ ald,
    float* __restrict__ num, float* __restrict__ denom) {
    int gw = (blockIdx.x * blockDim.x + threadIdx.x) >> 5;
    int lane = threadIdx.x & 31;
    if (gw >= EE) return;
    int src = __ldg(ei + gw);
    int dst = __ldg(ei + EE + gw);
    int h = lane >> 3;  // lane owns channels [lane*8, lane*8+8) -> head = lane/8
    float e = __ldg(als + src * HH + h) + __ldg(ald + dst * HH + h);
    e = (e >= 0.f) ? e : 0.2f * e;
    float w = __expf(e);
    if ((lane & 7) == 0) atomicAdd(denom + dst * HH + h, w);
    const float4* hsv = reinterpret_cast<const float4*>(hs + (size_t)src * HC);
    float* nr = num + (size_t)dst * HC;
    float4 v0 = __ldg(hsv + lane * 2);
    float4 v1 = __ldg(hsv + lane * 2 + 1);
    red_add_v4(nr + lane * 8,     w * v0.x, w * v0.y, w * v0.z, w * v0.w);
    red_add_v4(nr + lane * 8 + 4, w * v1.x, w * v1.y, w * v1.z, w * v1.w);
}

// ----------------- per-(t,r) finalize: intra = mean_h num/(denom+eps) -----------------
__global__ void intra_kernel(const float* __restrict__ num, const float* __restrict__ denom,
                             float* __restrict__ intra, int t, int r) {
    int idx = blockIdx.x * blockDim.x + threadIdx.x;
    if (idx >= NN * CC) return;
    int n = idx >> 6, c = idx & 63;
    float v = 0.f;
#pragma unroll
    for (int h = 0; h < HH; ++h)
        v += num[(size_t)n * HC + h * CC + c] / (denom[n * HH + h] + 1e-16f);
    intra[(((size_t)t * NN + n) * RR + r) * CC + c] = 0.25f * v;
}

// ----------------- relation scores: mean_n of tanh(h@W1+b1)@W2 -----------------
__global__ __launch_bounds__(256) void relation_kernel(
    const float* __restrict__ hmat, const float* __restrict__ W1,
    const float* __restrict__ b1, const float* __restrict__ W2,
    float* __restrict__ ssum) {
    extern __shared__ float sm[];
    float* sW1 = sm;            // 64*256
    float* sb1 = sm + 16384;    // 256
    float* sW2 = sm + 16640;    // 256
    float* sbins = sm + 16896;  // 8
    int tid = threadIdx.x;
    for (int i = tid; i < 16384; i += 256) sW1[i] = W1[i];
    if (tid < 256) { sb1[tid] = b1[tid]; sW2[tid] = W2[tid]; }
    if (tid < TT * RR) sbins[tid] = 0.f;
    __syncthreads();
    int lane = tid & 31;
    int gw = (blockIdx.x * blockDim.x + tid) >> 5;
    int nwarps = (gridDim.x * blockDim.x) >> 5;
    const int rows = TT * NN * RR;
    const int NR = NN * RR;
    for (int row = gw; row < rows; row += nwarps) {
        const float* hr = hmat + (size_t)row * CC;
        float h0 = hr[lane], h1 = hr[lane + 32];
        float a[8] = {0.f, 0.f, 0.f, 0.f, 0.f, 0.f, 0.f, 0.f};
#pragma unroll 8
        for (int k = 0; k < 64; ++k) {
            float hk = (k < 32) ? __shfl_sync(0xffffffffu, h0, k)
                                : __shfl_sync(0xffffffffu, h1, k - 32);
#pragma unroll
            for (int m = 0; m < 8; ++m) a[m] += hk * sW1[k * 256 + m * 32 + lane];
        }
        float acc = 0.f;
#pragma unroll
        for (int m = 0; m < 8; ++m) {
            int j = m * 32 + lane;
            acc += tanhf(a[m] + sb1[j]) * sW2[j];
        }
#pragma unroll
        for (int off = 16; off > 0; off >>= 1) acc += __shfl_down_sync(0xffffffffu, acc, off);
        if (lane == 0) atomicAdd(&sbins[(row / NR) * RR + (row & 1)], acc);
    }
    __syncthreads();
    if (tid < TT * RR) atomicAdd(&ssum[tid], sbins[tid]);
}

__global__ void beta_kernel(const float* __restrict__ ssum, float* __restrict__ beta) {
    int t = threadIdx.x;
    if (t < TT) {
        float s0 = ssum[t * RR + 0] * (1.0f / NN);
        float s1 = ssum[t * RR + 1] * (1.0f / NN);
        float m = fmaxf(s0, s1);
        float e0 = expf(s0 - m), e1 = expf(s1 - m);
        float inv = 1.f / (e0 + e1);
        beta[t * RR + 0] = e0 * inv;
        beta[t * RR + 1] = e1 * inv;
    }
}

__global__ void inter_kernel(const float* __restrict__ intra, const float* __restrict__ beta,
                             float* __restrict__ inter) {
    int idx = blockIdx.x * blockDim.x + threadIdx.x;
    if (idx >= TT * NN * CC) return;
    int t = idx / (NN * CC);
    int n = (idx / CC) % NN;
    int c = idx & 63;
    size_t base = ((size_t)(t * NN + n) * RR) * CC + c;
    inter[idx] = beta[t * RR] * intra[base] + beta[t * RR + 1] * intra[base + CC];
}

// ----------------- LSTM pointwise -----------------
__global__ void lstm_point_kernel(const float* __restrict__ gates, float* __restrict__ lh,
                                  float* __restrict__ lc, float* __restrict__ feats, int t) {
    int idx = blockIdx.x * blockDim.x + threadIdx.x;
    if (idx >= NN * CC) return;
    int n = idx >> 6, c = idx & 63;
    const float* g = gates + (size_t)n * HC;
    float gi = g[c], gf = g[64 + c], gg = g[128 + c], go = g[192 + c];
    float cc = sigmoidf_(gf) * lc[idx] + sigmoidf_(gi) * tanhf(gg);
    lc[idx] = cc;
    float hh = sigmoidf_(go) * tanhf(cc);
    lh[idx] = hh;
    feats[((size_t)n * TT + t) * CC + c] = hh;
}

// ----------------- temporal multi-head attention: warp per node -----------------
__global__ __launch_bounds__(256) void attn_kernel(
    const float* __restrict__ feats, const float* __restrict__ pos,
    const float* __restrict__ Wq, const float* __restrict__ Wk, const float* __restrict__ Wv,
    float* __restrict__ out) {
    extern __shared__ float sm[];
    float* sWq = sm;              // 4096
    float* sWk = sm + 4096;
    float* sWv = sm + 8192;
    float* spos = sm + 12288;     // 256
    float* wb = sm + 12544;       // 8 warps * 1088
    int tid = threadIdx.x;
    for (int i = tid; i < 4096; i += 256) {
        sWq[i] = Wq[i]; sWk[i] = Wk[i]; sWv[i] = Wv[i];
    }
    if (tid < 256) spos[tid] = pos[tid];
    __syncthreads();
    int wid = tid >> 5, lane = tid & 31;
    int n = blockIdx.x * 8 + wid;
    if (n >= NN) return;
    float* ti = wb + wid * 1088;
    float* q = ti + 256;
    float* k_ = q + 256;
    float* v = k_ + 256;
    float* a = v + 256;  // [h][tq][tk] : 64
#pragma unroll
    for (int m = 0; m < 8; ++m) {
        int o = m * 32 + lane;
        ti[o] = feats[(size_t)n * 256 + o] + spos[o];
    }
    __syncwarp();
#pragma unroll
    for (int m = 0; m < 8; ++m) {
        int o = m * 32 + lane;
        int t = o >> 6, c = o & 63;
        const float* tr = ti + t * 64;
        float aq = 0.f, ak = 0.f, av = 0.f;
#pragma unroll 8
        for (int k = 0; k < 64; ++k) {
            float tv = tr[k];
            aq += tv * sWq[k * 64 + c];
            ak += tv * sWk[k * 64 + c];
            av += tv * sWv[k * 64 + c];
        }
        q[o] = aq; k_[o] = ak; v[o] = av;
    }
    __syncwarp();
    if (lane < 16) {
        int h = lane >> 2, tq = lane & 3;
        float sc[4];
        for (int tk = 0; tk <= tq; ++tk) {
            float s = 0.f;
#pragma unroll
            for (int ch = 0; ch < 16; ++ch)
                s += q[tq * 64 + h * 16 + ch] * k_[tk * 64 + h * 16 + ch];
            sc[tk] = s * 0.5f;  // / sqrt(T), T=4
        }
        float mx = sc[0];
        for (int tk = 1; tk <= tq; ++tk) mx = fmaxf(mx, sc[tk]);
        float sum = 0.f;
        for (int tk = 0; tk <= tq; ++tk) { sc[tk] = __expf(sc[tk] - mx); sum += sc[tk]; }
        float inv = 1.f / sum;
        for (int tk = 0; tk < 4; ++tk)
            a[h * 16 + tq * 4 + tk] = (tk <= tq) ? sc[tk] * inv : 0.f;
    }
    __syncwarp();
#pragma unroll
    for (int m = 0; m < 8; ++m) {
        int o = m * 32 + lane;
        int tq = o >> 6, c = o & 63, h = c >> 4;
        float acc = 0.f;
#pragma unroll
        for (int tk = 0; tk < 4; ++tk)
            acc += a[h * 16 + tq * 4 + tk] * v[tk * 64 + c];
        out[(size_t)n * 256 + o] = acc;
    }
}

// ----------------- host launch -----------------
static float* symaddr(const void* sym) {
    void* p = nullptr;
    cudaGetSymbolAddress(&p, sym);
    return (float*)p;
}

extern "C" void kernel_launch(void* const* d_in, const int* in_sizes, int n_in,
                              void* d_out, int out_size) {
    const float* x = (const float*)d_in[0];
    const int* ei = (const int*)d_in[1];
    const float* W_src = (const float*)d_in[2];
    const float* W_dst = (const float*)d_in[3];
    const float* att_src = (const float*)d_in[4];
    const float* att_dst = (const float*)d_in[5];
    const float* ra_W1 = (const float*)d_in[6];
    const float* ra_b1 = (const float*)d_in[7];
    const float* ra_W2 = (const float*)d_in[8];
    const float* Wih = (const float*)d_in[9];
    const float* Whh = (const float*)d_in[10];
    const float* bih = (const float*)d_in[11];
    const float* bhh = (const float*)d_in[12];
    const float* pos = (const float*)d_in[13];
    const float* Wq = (const float*)d_in[14];
    const float* Wk = (const float*)d_in[15];
    const float* Wv = (const float*)d_in[16];
    float* out = (float*)d_out;

    float* hs = symaddr(g_hs);
    float* als = symaddr(g_als);
    float* ald = symaddr(g_ald);
    float* num = symaddr(g_num);
    float* denom = symaddr(g_denom);
    float* intra = symaddr(g_intra);
    float* ssum = symaddr(g_ssum);
    float* beta = symaddr(g_beta);
    float* inter = symaddr(g_inter);
    float* xg = symaddr(g_xg);
    float* gates = symaddr(g_gates);
    float* lh = symaddr(g_lh);
    float* lc = symaddr(g_lc);
    float* feats = symaddr(g_feats);
    float* WihT = symaddr(g_WihT);
    float* WhhT = symaddr(g_WhhT);
    float* biassum = symaddr(g_biassum);
    float* folds = symaddr(g_folds);
    float* foldd = symaddr(g_foldd);

    const int REL_SMEM = (16384 + 256 + 256 + 8) * 4;
    const int ATT_SMEM = (12544 + 8 * 1088) * 4;
    cudaFuncSetAttribute(relation_kernel, cudaFuncAttributeMaxDynamicSharedMemorySize, REL_SMEM);
    cudaFuncSetAttribute(attn_kernel, cudaFuncAttributeMaxDynamicSharedMemorySize, ATT_SMEM);

    // prep
    fold_att_kernel<<<2, 256>>>(W_src, W_dst, att_src, att_dst, folds, foldd);
    transpose_kernel<<<64, 256>>>(Wih, WihT, HC, DD);
    transpose_kernel<<<64, 256>>>(Whh, WhhT, HC, DD);
    bias_sum_kernel<<<1, 256>>>(bih, bhh, biassum);

    // GAT per (t, r)
    for (int t = 0; t < TT; ++t) {
        const float* xt = x + (size_t)t * NN * DD;
        for (int r = 0; r < RR; ++r) {
            gemm_k64<<<dim3(HC / 64, (NN + 63) / 64), 256>>>(
                xt, W_src + (size_t)r * DD * HC, hs, NN, HC, nullptr, nullptr);
            als_kernel<<<(NN * HH + 255) / 256, 256>>>(xt, folds + r * DD * HH,
                                                       foldd + r * DD * HH, als, ald);
            zero2_kernel<<<2048, 256>>>(num, NN * HC, denom, NN * HH);
            gat_edge_kernel<<<EE / 8, 256>>>(ei + ((size_t)(t * RR + r) * 2) * EE,
                                             hs, als, ald, num, denom);
            intra_kernel<<<(NN * CC + 255) / 256, 256>>>(num, denom, intra, t, r);
        }
    }

    // relation aggregation
    zero2_kernel<<<1, 32>>>(ssum, TT * RR, ssum, TT * RR);
    relation_kernel<<<444, 256, REL_SMEM>>>(intra, ra_W1, ra_b1, ra_W2, ssum);
    beta_kernel<<<1, 32>>>(ssum, beta);
    inter_kernel<<<(TT * NN * CC + 255) / 256, 256>>>(intra, beta, inter);

    // LSTM
    gemm_k64<<<dim3(HC / 64, (TT * NN + 63) / 64), 256>>>(inter, WihT, xg, TT * NN, HC,
                                                          nullptr, biassum);
    zero2_kernel<<<512, 256>>>(lh, NN * CC, lc, NN * CC);
    for (int t = 0; t < TT; ++t) {
        gemm_k64<<<dim3(HC / 64, (NN + 63) / 64), 256>>>(
            lh, WhhT, gates, NN, HC, xg + (size_t)t * NN * HC, nullptr);
        lstm_point_kernel<<<(NN * CC + 255) / 256, 256>>>(gates, lh, lc, feats, t);
    }

    // temporal attention
    attn_kernel<<<(NN + 7) / 8, 256, ATT_SMEM>>>(feats, pos, Wq, Wk, Wv, out);
}

// round 2
// speedup vs baseline: 1.5301x; 1.5301x over previous
#include <cuda_runtime.h>
#include <math.h>
#include <stdint.h>

#define TT 4
#define NN 20000
#define EE 320000
#define RR 2
#define DD 64
#define HH 4
#define CC 64
#define HC 256   // H*C
#define ZZ 8     // T*R

// ----------------- scratch (static device globals; no allocation) -----------------
__device__ __align__(16) float g_agg[ZZ * NN * HC];      // 163.8MB aggregated x-space
__device__ __align__(16) float g_als[ZZ * NN * HH];
__device__ __align__(16) float g_ald[ZZ * NN * HH];
__device__ __align__(16) float g_intra[TT * NN * RR * CC];
__device__ float g_ssum[TT * RR];
__device__ float g_beta[TT * RR];
__device__ __align__(16) float g_inter[TT * NN * CC];
__device__ __align__(16) float g_xg[TT * NN * HC];
__device__ __align__(16) float g_gates[NN * HC];
__device__ __align__(16) float g_lh[NN * CC];
__device__ __align__(16) float g_lc[NN * CC];
__device__ __align__(16) float g_feats[NN * TT * CC];
__device__ float g_WihT[DD * HC];
__device__ float g_WhhT[DD * HC];
__device__ float g_biassum[HC];
__device__ float g_folds[RR * DD * HH];
__device__ float g_foldd[RR * DD * HH];
__device__ float g_Bstack[RR * HC * CC];
__device__ int g_cnt[ZZ * NN];
__device__ int g_off[ZZ * (NN + 1)];
__device__ int g_pos[ZZ * NN];
__device__ int g_sorted[ZZ * EE];

// ----------------- helpers -----------------
__device__ __forceinline__ float sigmoidf_(float x) { return 1.0f / (1.0f + __expf(-x)); }

__device__ __forceinline__ float tanh_approx(float x) {
    float y; asm("tanh.approx.f32 %0, %1;" : "=f"(y) : "f"(x)); return y;
}
__device__ __forceinline__ unsigned long long fma2(unsigned long long a, unsigned long long b,
                                                   unsigned long long c) {
    unsigned long long d;
    asm("fma.rn.f32x2 %0, %1, %2, %3;" : "=l"(d) : "l"(a), "l"(b), "l"(c));
    return d;
}
__device__ __forceinline__ unsigned long long pack2s(float x) {
    unsigned long long u; asm("mov.b64 %0, {%1,%1};" : "=l"(u) : "f"(x)); return u;
}
__device__ __forceinline__ float2 ull2f(unsigned long long u) {
    float2 v; asm("mov.b64 {%0,%1}, %2;" : "=f"(v.x), "=f"(v.y) : "l"(u)); return v;
}

// ----------------- zeroing -----------------
__global__ void zero2_kernel(float* a, int na, float* b, int nb) {
    int i = blockIdx.x * blockDim.x + threadIdx.x;
    int st = gridDim.x * blockDim.x;
    for (int j = i; j < na; j += st) a[j] = 0.f;
    for (int j = i; j < nb; j += st) b[j] = 0.f;
}

// ----------------- prep kernels -----------------
__global__ void fold_att_kernel(const float* __restrict__ Wsrc, const float* __restrict__ Wdst,
                                const float* __restrict__ as_, const float* __restrict__ ad_,
                                float* __restrict__ fs, float* __restrict__ fd) {
    int idx = blockIdx.x * blockDim.x + threadIdx.x;
    if (idx >= RR * DD * HH) return;
    int r = idx / (DD * HH);
    int k = (idx / HH) % DD;
    int h = idx % HH;
    float accs = 0.f, accd = 0.f;
    for (int c = 0; c < CC; ++c) {
        accs += Wsrc[((size_t)(r * DD + k)) * HC + h * CC + c] * as_[(r * HH + h) * CC + c];
        accd += Wdst[((size_t)(r * DD + k)) * HC + h * CC + c] * ad_[(r * HH + h) * CC + c];
    }
    fs[idx] = accs;
    fd[idx] = accd;
}

__global__ void transpose_kernel(const float* __restrict__ W, float* __restrict__ WT,
                                 int rows, int cols) {
    int idx = blockIdx.x * blockDim.x + threadIdx.x;
    if (idx >= rows * cols) return;
    int r = idx / cols, c = idx % cols;
    WT[c * rows + r] = W[idx];
}

__global__ void bias_sum_kernel(const float* __restrict__ b1, const float* __restrict__ b2,
                                float* __restrict__ out) {
    int i = threadIdx.x;
    if (i < HC) out[i] = b1[i] + b2[i];
}

// Bstack[r][h*64+cin][cout] = W_src[r][cin][h*64+cout] * 0.25 (head-mean folded in)
__global__ void bstack_kernel(const float* __restrict__ Wsrc, float* __restrict__ Bst) {
    int idx = blockIdx.x * blockDim.x + threadIdx.x;
    if (idx >= RR * HC * CC) return;
    int r = idx / (HC * CC);
    int kk = (idx / CC) % HC;
    int co = idx % CC;
    int h = kk >> 6, ci = kk & 63;
    Bst[idx] = Wsrc[((size_t)(r * DD + ci)) * HC + h * 64 + co] * 0.25f;
}

// ----------------- attention-score projections (all z at once) -----------------
__global__ void als_all_kernel(const float* __restrict__ x, const float* __restrict__ fs,
                               const float* __restrict__ fd, float* __restrict__ als,
                               float* __restrict__ ald) {
    int idx = blockIdx.x * blockDim.x + threadIdx.x;
    if (idx >= ZZ * NN * HH) return;
    int z = idx / (NN * HH);
    int n = (idx / HH) % NN;
    int h = idx & 3;
    int t = z >> 1, r = z & 1;
    const float* xr = x + ((size_t)t * NN + n) * DD;
    const float* fsr = fs + r * DD * HH;
    const float* fdr = fd + r * DD * HH;
    float a = 0.f, b = 0.f;
#pragma unroll 8
    for (int k = 0; k < DD; ++k) {
        float xv = __ldg(xr + k);
        a += xv * fsr[k * HH + h];
        b += xv * fdr[k * HH + h];
    }
    als[idx] = a;
    ald[idx] = b;
}

// ----------------- CSR build (all 8 z batched) -----------------
__global__ void hist_kernel(const int* __restrict__ ei, int* __restrict__ cnt) {
    int i = blockIdx.x * blockDim.x + threadIdx.x;
    if (i >= ZZ * EE) return;
    int z = i / EE, e = i - z * EE;
    int dst = __ldg(ei + (size_t)z * 2 * EE + EE + e);
    atomicAdd(cnt + z * NN + dst, 1);
}

__global__ __launch_bounds__(1024) void scan_kernel(const int* __restrict__ cnt,
                                                    int* __restrict__ off,
                                                    int* __restrict__ pos) {
    __shared__ int ssums[1024];
    int z = blockIdx.x;
    const int* c = cnt + z * NN;
    int* o = off + z * (NN + 1);
    int* p = pos + z * NN;
    int tid = threadIdx.x;
    const int CH = (NN + 1023) / 1024;  // 20
    int base = tid * CH;
    int s = 0;
    for (int i = 0; i < CH; ++i) {
        int idx = base + i;
        if (idx < NN) s += c[idx];
    }
    ssums[tid] = s;
    __syncthreads();
    for (int d = 1; d < 1024; d <<= 1) {
        int v = (tid >= d) ? ssums[tid - d] : 0;
        __syncthreads();
        ssums[tid] += v;
        __syncthreads();
    }
    int run = (tid > 0) ? ssums[tid - 1] : 0;
    for (int i = 0; i < CH; ++i) {
        int idx = base + i;
        if (idx < NN) {
            o[idx] = run;
            p[idx] = run;
            run += c[idx];
        }
    }
    if (tid == 1023) o[NN] = ssums[1023];
}

__global__ void scatter_kernel(const int* __restrict__ ei, int* __restrict__ pos,
                               int* __restrict__ sorted) {
    int i = blockIdx.x * blockDim.x + threadIdx.x;
    if (i >= ZZ * EE) return;
    int z = i / EE, e = i - z * EE;
    int src = __ldg(ei + (size_t)z * 2 * EE + e);
    int dst = __ldg(ei + (size_t)z * 2 * EE + EE + e);
    int p = atomicAdd(pos + z * NN + dst, 1);
    sorted[(size_t)z * EE + p] = src;
}

// ----------------- gather: warp per (z, dst), x-space aggregation -----------------
__global__ __launch_bounds__(256) void gather_kernel(
    const int* __restrict__ off, const int* __restrict__ sorted,
    const float* __restrict__ x, const float* __restrict__ als,
    const float* __restrict__ ald, float* __restrict__ agg) {
    int z = blockIdx.y;
    int d = blockIdx.x * 8 + (threadIdx.x >> 5);
    int lane = threadIdx.x & 31;
    int h = lane >> 3;            // head for this lane
    int cb = (lane & 7) * 8;      // 8 input channels owned by this lane
    const float* xt = x + (size_t)(z >> 1) * NN * DD;
    const float* alz = als + (size_t)z * NN * HH;
    float aldv = __ldg(ald + ((size_t)z * NN + d) * HH + h);
    const int* offz = off + z * (NN + 1);
    const int* sz = sorted + (size_t)z * EE;
    int i = offz[d], iend = offz[d + 1];
    float4 A0 = {0.f, 0.f, 0.f, 0.f}, A1 = {0.f, 0.f, 0.f, 0.f};
    float den = 0.f;
    int src = (i < iend) ? __ldg(sz + i) : 0;
    while (i < iend) {
        float alsv = __ldg(alz + src * HH + h);
        const float4* xr = reinterpret_cast<const float4*>(xt + (size_t)src * DD + cb);
        float4 v0 = __ldg(xr);
        float4 v1 = __ldg(xr + 1);
        ++i;
        if (i < iend) src = __ldg(sz + i);
        float e = alsv + aldv;
        e = (e >= 0.f) ? e : 0.2f * e;
        float w = __expf(e);
        den += w;
        A0.x += w * v0.x; A0.y += w * v0.y; A0.z += w * v0.z; A0.w += w * v0.w;
        A1.x += w * v1.x; A1.y += w * v1.y; A1.z += w * v1.z; A1.w += w * v1.w;
    }
    float inv = 1.f / (den + 1e-16f);
    float* o = agg + ((size_t)z * NN + d) * HC + h * 64 + cb;
    reinterpret_cast<float4*>(o)[0] = make_float4(A0.x * inv, A0.y * inv, A0.z * inv, A0.w * inv);
    reinterpret_cast<float4*>(o)[1] = make_float4(A1.x * inv, A1.y * inv, A1.z * inv, A1.w * inv);
}

// ----------------- batched intra GEMM: intra(t,n,r,:) = agg_z @ Bstack_r  (K=256) -----------------
__global__ __launch_bounds__(256) void gemm_intra(const float* __restrict__ Abase,
                                                  const float* __restrict__ Bbase,
                                                  float* __restrict__ Cbase) {
    __shared__ float As[64][66];
    __shared__ float Bs[64][66];
    int z = blockIdx.y;
    int t = z >> 1, r = z & 1;
    const float* A = Abase + (size_t)z * NN * HC;
    const float* B = Bbase + (size_t)r * HC * CC;
    float* C = Cbase + (size_t)t * NN * RR * CC + r * CC;  // row stride RR*CC = 128
    int tid = threadIdx.x;
    int row0 = blockIdx.x * 64;
    int tx = tid & 15, ty = tid >> 4;
    unsigned long long acc2[4][2] = {};
    for (int kc = 0; kc < HC; kc += 64) {
#pragma unroll
        for (int i = 0; i < 16; ++i) {
            int idx = tid + i * 256;
            int rr = idx >> 6, cc = idx & 63;
            As[rr][cc] = (row0 + rr < NN) ? A[(size_t)(row0 + rr) * HC + kc + cc] : 0.f;
            Bs[rr][cc] = B[(size_t)(kc + rr) * CC + cc];
        }
        __syncthreads();
#pragma unroll 16
        for (int k = 0; k < 64; ++k) {
            unsigned long long b01 = *reinterpret_cast<const unsigned long long*>(&Bs[k][tx * 4]);
            unsigned long long b23 = *reinterpret_cast<const unsigned long long*>(&Bs[k][tx * 4 + 2]);
#pragma unroll
            for (int m = 0; m < 4; ++m) {
                unsigned long long am2 = pack2s(As[ty * 4 + m][k]);
                acc2[m][0] = fma2(am2, b01, acc2[m][0]);
                acc2[m][1] = fma2(am2, b23, acc2[m][1]);
            }
        }
        __syncthreads();
    }
#pragma unroll
    for (int m = 0; m < 4; ++m) {
        int gr = row0 + ty * 4 + m;
        if (gr < NN) {
            float2 lo = ull2f(acc2[m][0]);
            float2 hi = ull2f(acc2[m][1]);
            float* cr = C + (size_t)gr * (RR * CC) + tx * 4;
            cr[0] = lo.x; cr[1] = lo.y; cr[2] = hi.x; cr[3] = hi.y;
        }
    }
}

// ----------------- K=64 SGEMM (LSTM): C[M,NC] = A[M,64] @ B[64,NC] (+add +bias) -----------------
__global__ __launch_bounds__(256) void gemm_k64(
    const float* __restrict__ A, const float* __restrict__ B, float* __restrict__ C,
    int M, int NC, const float* __restrict__ addsrc, const float* __restrict__ bias) {
    __shared__ float As[64][66];
    __shared__ float Bs[64][66];
    int tid = threadIdx.x;
    int row0 = blockIdx.y * 64;
    int col0 = blockIdx.x * 64;
#pragma unroll
    for (int i = 0; i < 16; ++i) {
        int idx = tid + i * 256;
        int rr = idx >> 6, cc = idx & 63;
        As[rr][cc] = (row0 + rr < M) ? A[(size_t)(row0 + rr) * 64 + cc] : 0.f;
        Bs[rr][cc] = B[(size_t)rr * NC + col0 + cc];
    }
    __syncthreads();
    int tx = tid & 15, ty = tid >> 4;
    unsigned long long acc2[4][2] = {};
#pragma unroll 16
    for (int k = 0; k < 64; ++k) {
        unsigned long long b01 = *reinterpret_cast<const unsigned long long*>(&Bs[k][tx * 4]);
        unsigned long long b23 = *reinterpret_cast<const unsigned long long*>(&Bs[k][tx * 4 + 2]);
#pragma unroll
        for (int m = 0; m < 4; ++m) {
            unsigned long long am2 = pack2s(As[ty * 4 + m][k]);
            acc2[m][0] = fma2(am2, b01, acc2[m][0]);
            acc2[m][1] = fma2(am2, b23, acc2[m][1]);
        }
    }
#pragma unroll
    for (int m = 0; m < 4; ++m) {
        int gr = row0 + ty * 4 + m;
        if (gr < M) {
            float2 lo = ull2f(acc2[m][0]);
            float2 hi = ull2f(acc2[m][1]);
            float v[4] = {lo.x, lo.y, hi.x, hi.y};
#pragma unroll
            for (int n = 0; n < 4; ++n) {
                int gc = col0 + tx * 4 + n;
                float vv = v[n];
                if (addsrc) vv += addsrc[(size_t)gr * NC + gc];
                if (bias) vv += bias[gc];
                C[(size_t)gr * NC + gc] = vv;
            }
        }
    }
}

// ----------------- relation scores: mean_n of tanh(h@W1+b1)@W2 -----------------
__global__ __launch_bounds__(256) void relation_kernel(
    const float* __restrict__ hmat, const float* __restrict__ W1,
    const float* __restrict__ b1, const float* __restrict__ W2,
    float* __restrict__ ssum) {
    extern __shared__ float sm[];
    float2* sW1v = reinterpret_cast<float2*>(sm);  // 8192 float2 (16384 floats)
    float* sb1 = sm + 16384;                       // 256
    float* sW2 = sm + 16640;                       // 256
    float* sbins = sm + 16896;                     // 8
    int tid = threadIdx.x;
    for (int i = tid; i < 8192; i += 256) {
        int k = i >> 7;
        int rem = i & 127;
        int p = rem >> 5, l = rem & 31;
        int j1 = k * 256 + p * 64 + l;
        sW1v[i] = make_float2(W1[j1], W1[j1 + 32]);
    }
    if (tid < 256) { sb1[tid] = b1[tid]; sW2[tid] = W2[tid]; }
    if (tid < TT * RR) sbins[tid] = 0.f;
    __syncthreads();
    int lane = tid & 31;
    int gw = (blockIdx.x * blockDim.x + tid) >> 5;
    int nwarps = (gridDim.x * blockDim.x) >> 5;
    const int rows = TT * NN * RR;
    const int NR = NN * RR;
    for (int row = gw; row < rows; row += nwarps) {
        const float* hr = hmat + (size_t)row * CC;
        float h0 = hr[lane], h1 = hr[lane + 32];
        unsigned long long a2[4] = {0ull, 0ull, 0ull, 0ull};
        const unsigned long long* wbase =
            reinterpret_cast<const unsigned long long*>(sW1v) + lane;
#pragma unroll 8
        for (int k = 0; k < 32; ++k) {
            unsigned long long hk2 = pack2s(__shfl_sync(0xffffffffu, h0, k));
            const unsigned long long* w = wbase + k * 128;
            a2[0] = fma2(hk2, w[0], a2[0]);
            a2[1] = fma2(hk2, w[32], a2[1]);
            a2[2] = fma2(hk2, w[64], a2[2]);
            a2[3] = fma2(hk2, w[96], a2[3]);
        }
#pragma unroll 8
        for (int k = 0; k < 32; ++k) {
            unsigned long long hk2 = pack2s(__shfl_sync(0xffffffffu, h1, k));
            const unsigned long long* w = wbase + (k + 32) * 128;
            a2[0] = fma2(hk2, w[0], a2[0]);
            a2[1] = fma2(hk2, w[32], a2[1]);
            a2[2] = fma2(hk2, w[64], a2[2]);
            a2[3] = fma2(hk2, w[96], a2[3]);
        }
        float acc = 0.f;
#pragma unroll
        for (int p = 0; p < 4; ++p) {
            float2 av = ull2f(a2[p]);
            int j1 = p * 64 + lane, j2 = j1 + 32;
            acc += tanh_approx(av.x + sb1[j1]) * sW2[j1];
            acc += tanh_approx(av.y + sb1[j2]) * sW2[j2];
        }
#pragma unroll
        for (int off2 = 16; off2 > 0; off2 >>= 1)
            acc += __shfl_down_sync(0xffffffffu, acc, off2);
        if (lane == 0) atomicAdd(&sbins[(row / NR) * RR + (row & 1)], acc);
    }
    __syncthreads();
    if (tid < TT * RR) atomicAdd(&ssum[tid], sbins[tid]);
}

__global__ void beta_kernel(const float* __restrict__ ssum, float* __restrict__ beta) {
    int t = threadIdx.x;
    if (t < TT) {
        float s0 = ssum[t * RR + 0] * (1.0f / NN);
        float s1 = ssum[t * RR + 1] * (1.0f / NN);
        float m = fmaxf(s0, s1);
        float e0 = expf(s0 - m), e1 = expf(s1 - m);
        float inv = 1.f / (e0 + e1);
        beta[t * RR + 0] = e0 * inv;
        beta[t * RR + 1] = e1 * inv;
    }
}

__global__ void inter_kernel(const float* __restrict__ intra, const float* __restrict__ beta,
                             float* __restrict__ inter) {
    int idx = blockIdx.x * blockDim.x + threadIdx.x;
    if (idx >= TT * NN * CC) return;
    int t = idx / (NN * CC);
    size_t nbase = (size_t)(idx / CC) * RR * CC + (idx & 63);
    inter[idx] = beta[t * RR] * intra[nbase] + beta[t * RR + 1] * intra[nbase + CC];
}

// ----------------- LSTM pointwise -----------------
__global__ void lstm_point_kernel(const float* __restrict__ gates, float* __restrict__ lh,
                                  float* __restrict__ lc, float* __restrict__ feats, int t) {
    int idx = blockIdx.x * blockDim.x + threadIdx.x;
    if (idx >= NN * CC) return;
    int n = idx >> 6, c = idx & 63;
    const float* g = gates + (size_t)n * HC;
    float gi = g[c], gf = g[64 + c], gg = g[128 + c], go = g[192 + c];
    float cc = sigmoidf_(gf) * lc[idx] + sigmoidf_(gi) * tanhf(gg);
    lc[idx] = cc;
    float hh = sigmoidf_(go) * tanhf(cc);
    lh[idx] = hh;
    feats[((size_t)n * TT + t) * CC + c] = hh;
}

// ----------------- temporal multi-head attention: warp per node -----------------
__global__ __launch_bounds__(256) void attn_kernel(
    const float* __restrict__ feats, const float* __restrict__ pos,
    const float* __restrict__ Wq, const float* __restrict__ Wk, const float* __restrict__ Wv,
    float* __restrict__ out) {
    extern __shared__ float sm[];
    float* sWq = sm;
    float* sWk = sm + 4096;
    float* sWv = sm + 8192;
    float* spos = sm + 12288;
    float* wb = sm + 12544;
    int tid = threadIdx.x;
    for (int i = tid; i < 4096; i += 256) {
        sWq[i] = Wq[i]; sWk[i] = Wk[i]; sWv[i] = Wv[i];
    }
    if (tid < 256) spos[tid] = pos[tid];
    __syncthreads();
    int wid = tid >> 5, lane = tid & 31;
    int n = blockIdx.x * 8 + wid;
    if (n >= NN) return;
    float* ti = wb + wid * 1088;
    float* q = ti + 256;
    float* k_ = q + 256;
    float* v = k_ + 256;
    float* a = v + 256;
#pragma unroll
    for (int m = 0; m < 8; ++m) {
        int o = m * 32 + lane;
        ti[o] = feats[(size_t)n * 256 + o] + spos[o];
    }
    __syncwarp();
#pragma unroll
    for (int m = 0; m < 8; ++m) {
        int o = m * 32 + lane;
        int t = o >> 6, c = o & 63;
        const float* tr = ti + t * 64;
        float aq = 0.f, ak = 0.f, av = 0.f;
#pragma unroll 8
        for (int k = 0; k < 64; ++k) {
            float tv = tr[k];
            aq += tv * sWq[k * 64 + c];
            ak += tv * sWk[k * 64 + c];
            av += tv * sWv[k * 64 + c];
        }
        q[o] = aq; k_[o] = ak; v[o] = av;
    }
    __syncwarp();
    if (lane < 16) {
        int h = lane >> 2, tq = lane & 3;
        float sc[4];
        for (int tk = 0; tk <= tq; ++tk) {
            float s = 0.f;
#pragma unroll
            for (int ch = 0; ch < 16; ++ch)
                s += q[tq * 64 + h * 16 + ch] * k_[tk * 64 + h * 16 + ch];
            sc[tk] = s * 0.5f;
        }
        float mx = sc[0];
        for (int tk = 1; tk <= tq; ++tk) mx = fmaxf(mx, sc[tk]);
        float sum = 0.f;
        for (int tk = 0; tk <= tq; ++tk) { sc[tk] = __expf(sc[tk] - mx); sum += sc[tk]; }
        float inv = 1.f / sum;
        for (int tk = 0; tk < 4; ++tk)
            a[h * 16 + tq * 4 + tk] = (tk <= tq) ? sc[tk] * inv : 0.f;
    }
    __syncwarp();
#pragma unroll
    for (int m = 0; m < 8; ++m) {
        int o = m * 32 + lane;
        int tq = o >> 6, c = o & 63, h = c >> 4;
        float acc = 0.f;
#pragma unroll
        for (int tk = 0; tk < 4; ++tk)
            acc += a[h * 16 + tq * 4 + tk] * v[tk * 64 + c];
        out[(size_t)n * 256 + o] = acc;
    }
}

// ----------------- host launch -----------------
template <typename T>
static T* symaddr(const void* sym) {
    void* p = nullptr;
    cudaGetSymbolAddress(&p, sym);
    return (T*)p;
}

extern "C" void kernel_launch(void* const* d_in, const int* in_sizes, int n_in,
                              void* d_out, int out_size) {
    const float* x = (const float*)d_in[0];
    const int* ei = (const int*)d_in[1];
    const float* W_src = (const float*)d_in[2];
    const float* W_dst = (const float*)d_in[3];
    const float* att_src = (const float*)d_in[4];
    const float* att_dst = (const float*)d_in[5];
    const float* ra_W1 = (const float*)d_in[6];
    const float* ra_b1 = (const float*)d_in[7];
    const float* ra_W2 = (const float*)d_in[8];
    const float* Wih = (const float*)d_in[9];
    const float* Whh = (const float*)d_in[10];
    const float* bih = (const float*)d_in[11];
    const float* bhh = (const float*)d_in[12];
    const float* pos = (const float*)d_in[13];
    const float* Wq = (const float*)d_in[14];
    const float* Wk = (const float*)d_in[15];
    const float* Wv = (const float*)d_in[16];
    float* out = (float*)d_out;

    float* agg = symaddr<float>(g_agg);
    float* als = symaddr<float>(g_als);
    float* ald = symaddr<float>(g_ald);
    float* intra = symaddr<float>(g_intra);
    float* ssum = symaddr<float>(g_ssum);
    float* beta = symaddr<float>(g_beta);
    float* inter = symaddr<float>(g_inter);
    float* xg = symaddr<float>(g_xg);
    float* gates = symaddr<float>(g_gates);
    float* lh = symaddr<float>(g_lh);
    float* lc = symaddr<float>(g_lc);
    float* feats = symaddr<float>(g_feats);
    float* WihT = symaddr<float>(g_WihT);
    float* WhhT = symaddr<float>(g_WhhT);
    float* biassum = symaddr<float>(g_biassum);
    float* folds = symaddr<float>(g_folds);
    float* foldd = symaddr<float>(g_foldd);
    float* Bstack = symaddr<float>(g_Bstack);
    int* cnt = symaddr<int>(g_cnt);
    int* off = symaddr<int>(g_off);
    int* posb = symaddr<int>(g_pos);
    int* sorted = symaddr<int>(g_sorted);

    const int REL_SMEM = (16384 + 256 + 256 + 8) * 4;
    const int ATT_SMEM = (12544 + 8 * 1088) * 4;
    cudaFuncSetAttribute(relation_kernel, cudaFuncAttributeMaxDynamicSharedMemorySize, REL_SMEM);
    cudaFuncSetAttribute(attn_kernel, cudaFuncAttributeMaxDynamicSharedMemorySize, ATT_SMEM);

    // ---- prep
    fold_att_kernel<<<2, 256>>>(W_src, W_dst, att_src, att_dst, folds, foldd);
    transpose_kernel<<<64, 256>>>(Wih, WihT, HC, DD);
    transpose_kernel<<<64, 256>>>(Whh, WhhT, HC, DD);
    bias_sum_kernel<<<1, 256>>>(bih, bhh, biassum);
    bstack_kernel<<<128, 256>>>(W_src, Bstack);

    // ---- CSR build (all z)
    cudaMemsetAsync(cnt, 0, (size_t)ZZ * NN * sizeof(int), 0);
    hist_kernel<<<(ZZ * EE) / 256, 256>>>(ei, cnt);
    scan_kernel<<<ZZ, 1024>>>(cnt, off, posb);
    scatter_kernel<<<(ZZ * EE) / 256, 256>>>(ei, posb, sorted);

    // ---- attention coefficients + gather (all z)
    als_all_kernel<<<(ZZ * NN * HH) / 256, 256>>>(x, folds, foldd, als, ald);
    gather_kernel<<<dim3(NN / 8, ZZ), 256>>>(off, sorted, x, als, ald, agg);

    // ---- batched intra GEMM
    gemm_intra<<<dim3((NN + 63) / 64, ZZ), 256>>>(agg, Bstack, intra);

    // ---- relation aggregation
    cudaMemsetAsync(ssum, 0, TT * RR * sizeof(float), 0);
    relation_kernel<<<444, 256, REL_SMEM>>>(intra, ra_W1, ra_b1, ra_W2, ssum);
    beta_kernel<<<1, 32>>>(ssum, beta);
    inter_kernel<<<(TT * NN * CC + 255) / 256, 256>>>(intra, beta, inter);

    // ---- LSTM
    gemm_k64<<<dim3(HC / 64, (TT * NN + 63) / 64), 256>>>(inter, WihT, xg, TT * NN, HC,
                                                          nullptr, biassum);
    cudaMemsetAsync(lh, 0, (size_t)NN * CC * sizeof(float), 0);
    cudaMemsetAsync(lc, 0, (size_t)NN * CC * sizeof(float), 0);
    for (int t = 0; t < TT; ++t) {
        gemm_k64<<<dim3(HC / 64, (NN + 63) / 64), 256>>>(
            lh, WhhT, gates, NN, HC, xg + (size_t)t * NN * HC, nullptr);
        lstm_point_kernel<<<(NN * CC + 255) / 256, 256>>>(gates, lh, lc, feats, t);
    }

    // ---- temporal attention
    attn_kernel<<<(NN + 7) / 8, 256, ATT_SMEM>>>(feats, pos, Wq, Wk, Wv, out);
}

// round 3
// speedup vs baseline: 1.9094x; 1.2479x over previous
#include <cuda_runtime.h>
#include <math.h>
#include <stdint.h>

#define TT 4
#define NN 20000
#define EE 320000
#define RR 2
#define DD 64
#define HH 4
#define CC 64
#define HC 256   // H*C
#define ZZ 8     // T*R

// ----------------- scratch (static device globals; no allocation) -----------------
__device__ __align__(16) float g_agg[ZZ * NN * HC];
__device__ __align__(16) float g_als[ZZ * NN * HH];
__device__ __align__(16) float g_ald[ZZ * NN * HH];
__device__ __align__(16) float g_intra[TT * NN * RR * CC];
__device__ float g_ssum[TT * RR];
__device__ float g_beta[TT * RR];
__device__ __align__(16) float g_inter[TT * NN * CC];
__device__ __align__(16) float g_xg[TT * NN * HC];
__device__ __align__(16) float g_gates[NN * HC];
__device__ __align__(16) float g_lh[NN * CC];
__device__ __align__(16) float g_lc[NN * CC];
__device__ __align__(16) float g_feats[NN * TT * CC];
__device__ float g_WihT[DD * HC];
__device__ float g_WhhT[DD * HC];
__device__ float g_biassum[HC];
__device__ float g_folds[RR * DD * HH];
__device__ float g_foldd[RR * DD * HH];
__device__ float g_Bstack[RR * HC * CC];
__device__ int g_cnt[ZZ * NN];
__device__ int g_off[ZZ * (NN + 1)];
__device__ int g_pos[ZZ * NN];
__device__ int g_sorted[ZZ * EE];

// ----------------- helpers -----------------
__device__ __forceinline__ float sigmoidf_(float x) { return 1.0f / (1.0f + __expf(-x)); }

__device__ __forceinline__ float tanh_approx(float x) {
    float y; asm("tanh.approx.f32 %0, %1;" : "=f"(y) : "f"(x)); return y;
}
__device__ __forceinline__ unsigned long long fma2(unsigned long long a, unsigned long long b,
                                                   unsigned long long c) {
    unsigned long long d;
    asm("fma.rn.f32x2 %0, %1, %2, %3;" : "=l"(d) : "l"(a), "l"(b), "l"(c));
    return d;
}
__device__ __forceinline__ unsigned long long pack2s(float x) {
    unsigned long long u; asm("mov.b64 %0, {%1,%1};" : "=l"(u) : "f"(x)); return u;
}
__device__ __forceinline__ float2 ull2f(unsigned long long u) {
    float2 v; asm("mov.b64 {%0,%1}, %2;" : "=f"(v.x), "=f"(v.y) : "l"(u)); return v;
}

// ----------------- prep kernels -----------------
__global__ void fold_att_kernel(const float* __restrict__ Wsrc, const float* __restrict__ Wdst,
                                const float* __restrict__ as_, const float* __restrict__ ad_,
                                float* __restrict__ fs, float* __restrict__ fd) {
    int idx = blockIdx.x * blockDim.x + threadIdx.x;
    if (idx >= RR * DD * HH) return;
    int r = idx / (DD * HH);
    int k = (idx / HH) % DD;
    int h = idx % HH;
    float accs = 0.f, accd = 0.f;
    for (int c = 0; c < CC; ++c) {
        accs += Wsrc[((size_t)(r * DD + k)) * HC + h * CC + c] * as_[(r * HH + h) * CC + c];
        accd += Wdst[((size_t)(r * DD + k)) * HC + h * CC + c] * ad_[(r * HH + h) * CC + c];
    }
    fs[idx] = accs;
    fd[idx] = accd;
}

__global__ void transpose_kernel(const float* __restrict__ W, float* __restrict__ WT,
                                 int rows, int cols) {
    int idx = blockIdx.x * blockDim.x + threadIdx.x;
    if (idx >= rows * cols) return;
    int r = idx / cols, c = idx % cols;
    WT[c * rows + r] = W[idx];
}

__global__ void bias_sum_kernel(const float* __restrict__ b1, const float* __restrict__ b2,
                                float* __restrict__ out) {
    int i = threadIdx.x;
    if (i < HC) out[i] = b1[i] + b2[i];
}

__global__ void bstack_kernel(const float* __restrict__ Wsrc, float* __restrict__ Bst) {
    int idx = blockIdx.x * blockDim.x + threadIdx.x;
    if (idx >= RR * HC * CC) return;
    int r = idx / (HC * CC);
    int kk = (idx / CC) % HC;
    int co = idx % CC;
    int h = kk >> 6, ci = kk & 63;
    Bst[idx] = Wsrc[((size_t)(r * DD + ci)) * HC + h * 64 + co] * 0.25f;
}

// ----------------- attention-score projections (all z at once) -----------------
__global__ void als_all_kernel(const float* __restrict__ x, const float* __restrict__ fs,
                               const float* __restrict__ fd, float* __restrict__ als,
                               float* __restrict__ ald) {
    int idx = blockIdx.x * blockDim.x + threadIdx.x;
    if (idx >= ZZ * NN * HH) return;
    int z = idx / (NN * HH);
    int n = (idx / HH) % NN;
    int h = idx & 3;
    int t = z >> 1, r = z & 1;
    const float* xr = x + ((size_t)t * NN + n) * DD;
    const float* fsr = fs + r * DD * HH;
    const float* fdr = fd + r * DD * HH;
    float a = 0.f, b = 0.f;
#pragma unroll 8
    for (int k = 0; k < DD; ++k) {
        float xv = __ldg(xr + k);
        a += xv * fsr[k * HH + h];
        b += xv * fdr[k * HH + h];
    }
    als[idx] = a;
    ald[idx] = b;
}

// ----------------- CSR build (all 8 z batched) -----------------
__global__ void hist_kernel(const int* __restrict__ ei, int* __restrict__ cnt) {
    int i = blockIdx.x * blockDim.x + threadIdx.x;
    if (i >= ZZ * EE) return;
    int z = i / EE, e = i - z * EE;
    int dst = __ldg(ei + (size_t)z * 2 * EE + EE + e);
    atomicAdd(cnt + z * NN + dst, 1);
}

__global__ __launch_bounds__(1024) void scan_kernel(const int* __restrict__ cnt,
                                                    int* __restrict__ off,
                                                    int* __restrict__ pos) {
    __shared__ int ssums[1024];
    int z = blockIdx.x;
    const int* c = cnt + z * NN;
    int* o = off + z * (NN + 1);
    int* p = pos + z * NN;
    int tid = threadIdx.x;
    const int CH = (NN + 1023) / 1024;  // 20
    int base = tid * CH;
    int s = 0;
    for (int i = 0; i < CH; ++i) {
        int idx = base + i;
        if (idx < NN) s += c[idx];
    }
    ssums[tid] = s;
    __syncthreads();
    for (int d = 1; d < 1024; d <<= 1) {
        int v = (tid >= d) ? ssums[tid - d] : 0;
        __syncthreads();
        ssums[tid] += v;
        __syncthreads();
    }
    int run = (tid > 0) ? ssums[tid - 1] : 0;
    for (int i = 0; i < CH; ++i) {
        int idx = base + i;
        if (idx < NN) {
            o[idx] = run;
            p[idx] = run;
            run += c[idx];
        }
    }
    if (tid == 1023) o[NN] = ssums[1023];
}

__global__ void scatter_kernel(const int* __restrict__ ei, int* __restrict__ pos,
                               int* __restrict__ sorted) {
    int i = blockIdx.x * blockDim.x + threadIdx.x;
    if (i >= ZZ * EE) return;
    int z = i / EE, e = i - z * EE;
    int src = __ldg(ei + (size_t)z * 2 * EE + e);
    int dst = __ldg(ei + (size_t)z * 2 * EE + EE + e);
    int p = atomicAdd(pos + z * NN + dst, 1);
    sorted[(size_t)z * EE + p] = src;
}

// ----------------- gather: warp per (z, dst). Lane owns 2 x-channels, all 4 heads. ---------
__global__ __launch_bounds__(256) void gather_kernel(
    const int* __restrict__ off, const int* __restrict__ sorted,
    const float* __restrict__ x, const float* __restrict__ als,
    const float* __restrict__ ald, float* __restrict__ agg) {
    int z = blockIdx.y;
    int d = blockIdx.x * 8 + (threadIdx.x >> 5);
    int lane = threadIdx.x & 31;
    const float* xt = x + (size_t)(z >> 1) * NN * DD;
    const float4* alz = reinterpret_cast<const float4*>(als) + (size_t)z * NN;
    float4 aldv = __ldg(reinterpret_cast<const float4*>(ald) + (size_t)z * NN + d);
    const int* offz = off + z * (NN + 1);
    const int* sz = sorted + (size_t)z * EE;
    int i = offz[d], iend = offz[d + 1];
    float2 A0 = {0.f, 0.f}, A1 = {0.f, 0.f}, A2 = {0.f, 0.f}, A3 = {0.f, 0.f};
    float d0 = 0.f, d1 = 0.f, d2 = 0.f, d3 = 0.f;
    int src = (i < iend) ? __ldg(sz + i) : 0;
    while (i < iend) {
        float4 asv = __ldg(alz + src);
        float2 xv = __ldg(reinterpret_cast<const float2*>(xt + (size_t)src * DD) + lane);
        ++i;
        if (i < iend) src = __ldg(sz + i);
        float e0 = asv.x + aldv.x; e0 = (e0 >= 0.f) ? e0 : 0.2f * e0; float w0 = __expf(e0);
        float e1 = asv.y + aldv.y; e1 = (e1 >= 0.f) ? e1 : 0.2f * e1; float w1 = __expf(e1);
        float e2 = asv.z + aldv.z; e2 = (e2 >= 0.f) ? e2 : 0.2f * e2; float w2 = __expf(e2);
        float e3 = asv.w + aldv.w; e3 = (e3 >= 0.f) ? e3 : 0.2f * e3; float w3 = __expf(e3);
        d0 += w0; d1 += w1; d2 += w2; d3 += w3;
        A0.x += w0 * xv.x; A0.y += w0 * xv.y;
        A1.x += w1 * xv.x; A1.y += w1 * xv.y;
        A2.x += w2 * xv.x; A2.y += w2 * xv.y;
        A3.x += w3 * xv.x; A3.y += w3 * xv.y;
    }
    float i0 = 1.f / (d0 + 1e-16f), i1 = 1.f / (d1 + 1e-16f);
    float i2 = 1.f / (d2 + 1e-16f), i3 = 1.f / (d3 + 1e-16f);
    float2* o = reinterpret_cast<float2*>(agg + ((size_t)z * NN + d) * HC) + lane;
    o[0]  = make_float2(A0.x * i0, A0.y * i0);
    o[32] = make_float2(A1.x * i1, A1.y * i1);
    o[64] = make_float2(A2.x * i2, A2.y * i2);
    o[96] = make_float2(A3.x * i3, A3.y * i3);
}

// ----------------- batched intra GEMM: intra(t,n,r,:) = agg_z @ Bstack_r  (K=256) ----------
__global__ __launch_bounds__(256) void gemm_intra(const float* __restrict__ Abase,
                                                  const float* __restrict__ Bbase,
                                                  float* __restrict__ Cbase) {
    __shared__ float As[64][66];
    __shared__ float Bs[64][66];
    int z = blockIdx.y;
    int t = z >> 1, r = z & 1;
    const float* A = Abase + (size_t)z * NN * HC;
    const float* B = Bbase + (size_t)r * HC * CC;
    float* C = Cbase + (size_t)t * NN * RR * CC + r * CC;
    int tid = threadIdx.x;
    int row0 = blockIdx.x * 64;
    int tx = tid & 15, ty = tid >> 4;
    unsigned long long acc2[4][2] = {};
    for (int kc = 0; kc < HC; kc += 64) {
#pragma unroll
        for (int i = 0; i < 16; ++i) {
            int idx = tid + i * 256;
            int rr = idx >> 6, cc = idx & 63;
            As[rr][cc] = (row0 + rr < NN) ? A[(size_t)(row0 + rr) * HC + kc + cc] : 0.f;
            Bs[rr][cc] = B[(size_t)(kc + rr) * CC + cc];
        }
        __syncthreads();
#pragma unroll 16
        for (int k = 0; k < 64; ++k) {
            unsigned long long b01 = *reinterpret_cast<const unsigned long long*>(&Bs[k][tx * 4]);
            unsigned long long b23 = *reinterpret_cast<const unsigned long long*>(&Bs[k][tx * 4 + 2]);
#pragma unroll
            for (int m = 0; m < 4; ++m) {
                unsigned long long am2 = pack2s(As[ty * 4 + m][k]);
                acc2[m][0] = fma2(am2, b01, acc2[m][0]);
                acc2[m][1] = fma2(am2, b23, acc2[m][1]);
            }
        }
        __syncthreads();
    }
#pragma unroll
    for (int m = 0; m < 4; ++m) {
        int gr = row0 + ty * 4 + m;
        if (gr < NN) {
            float2 lo = ull2f(acc2[m][0]);
            float2 hi = ull2f(acc2[m][1]);
            float* cr = C + (size_t)gr * (RR * CC) + tx * 4;
            cr[0] = lo.x; cr[1] = lo.y; cr[2] = hi.x; cr[3] = hi.y;
        }
    }
}

// ----------------- K=64 SGEMM (LSTM): C[M,NC] = A[M,64] @ B[64,NC] (+add +bias) -----------
__global__ __launch_bounds__(256) void gemm_k64(
    const float* __restrict__ A, const float* __restrict__ B, float* __restrict__ C,
    int M, int NC, const float* __restrict__ addsrc, const float* __restrict__ bias) {
    __shared__ float As[64][66];
    __shared__ float Bs[64][66];
    int tid = threadIdx.x;
    int row0 = blockIdx.y * 64;
    int col0 = blockIdx.x * 64;
#pragma unroll
    for (int i = 0; i < 16; ++i) {
        int idx = tid + i * 256;
        int rr = idx >> 6, cc = idx & 63;
        As[rr][cc] = (row0 + rr < M) ? A[(size_t)(row0 + rr) * 64 + cc] : 0.f;
        Bs[rr][cc] = B[(size_t)rr * NC + col0 + cc];
    }
    __syncthreads();
    int tx = tid & 15, ty = tid >> 4;
    unsigned long long acc2[4][2] = {};
#pragma unroll 16
    for (int k = 0; k < 64; ++k) {
        unsigned long long b01 = *reinterpret_cast<const unsigned long long*>(&Bs[k][tx * 4]);
        unsigned long long b23 = *reinterpret_cast<const unsigned long long*>(&Bs[k][tx * 4 + 2]);
#pragma unroll
        for (int m = 0; m < 4; ++m) {
            unsigned long long am2 = pack2s(As[ty * 4 + m][k]);
            acc2[m][0] = fma2(am2, b01, acc2[m][0]);
            acc2[m][1] = fma2(am2, b23, acc2[m][1]);
        }
    }
#pragma unroll
    for (int m = 0; m < 4; ++m) {
        int gr = row0 + ty * 4 + m;
        if (gr < M) {
            float2 lo = ull2f(acc2[m][0]);
            float2 hi = ull2f(acc2[m][1]);
            float v[4] = {lo.x, lo.y, hi.x, hi.y};
#pragma unroll
            for (int n = 0; n < 4; ++n) {
                int gc = col0 + tx * 4 + n;
                float vv = v[n];
                if (addsrc) vv += addsrc[(size_t)gr * NC + gc];
                if (bias) vv += bias[gc];
                C[(size_t)gr * NC + gc] = vv;
            }
        }
    }
}

// ----------------- relation scores: 4 rows per warp iteration -----------------
__global__ __launch_bounds__(256) void relation_kernel(
    const float* __restrict__ hmat, const float* __restrict__ W1,
    const float* __restrict__ b1, const float* __restrict__ W2,
    float* __restrict__ ssum) {
    extern __shared__ float sm[];
    float2* sW1v = reinterpret_cast<float2*>(sm);  // 8192 float2
    float* sb1 = sm + 16384;
    float* sW2 = sm + 16640;
    float* sbins = sm + 16896;
    int tid = threadIdx.x;
    for (int i = tid; i < 8192; i += 256) {
        int k = i >> 7;
        int rem = i & 127;
        int p = rem >> 5, l = rem & 31;
        int j1 = k * 256 + p * 64 + l;
        sW1v[i] = make_float2(W1[j1], W1[j1 + 32]);
    }
    if (tid < 256) { sb1[tid] = b1[tid]; sW2[tid] = W2[tid]; }
    if (tid < TT * RR) sbins[tid] = 0.f;
    __syncthreads();
    int lane = tid & 31;
    int gw = (blockIdx.x * blockDim.x + tid) >> 5;
    int nwarps = (gridDim.x * blockDim.x) >> 5;
    const int groups = (TT * NN * RR) / 4;  // 40000, groups never span t
    const int NR = NN * RR;
    const unsigned long long* wbase = reinterpret_cast<const unsigned long long*>(sW1v) + lane;
    for (int g = gw; g < groups; g += nwarps) {
        int row = g * 4;
        const float* hr = hmat + (size_t)row * CC;
        float h0[4], h1[4];
#pragma unroll
        for (int j = 0; j < 4; ++j) {
            h0[j] = hr[j * 64 + lane];
            h1[j] = hr[j * 64 + lane + 32];
        }
        unsigned long long a2[4][4] = {};
#pragma unroll 4
        for (int k = 0; k < 32; ++k) {
            const unsigned long long* w = wbase + k * 128;
            unsigned long long w0 = w[0], w1 = w[32], w2 = w[64], w3 = w[96];
#pragma unroll
            for (int j = 0; j < 4; ++j) {
                unsigned long long hk2 = pack2s(__shfl_sync(0xffffffffu, h0[j], k));
                a2[j][0] = fma2(hk2, w0, a2[j][0]);
                a2[j][1] = fma2(hk2, w1, a2[j][1]);
                a2[j][2] = fma2(hk2, w2, a2[j][2]);
                a2[j][3] = fma2(hk2, w3, a2[j][3]);
            }
        }
#pragma unroll 4
        for (int k = 0; k < 32; ++k) {
            const unsigned long long* w = wbase + (k + 32) * 128;
            unsigned long long w0 = w[0], w1 = w[32], w2 = w[64], w3 = w[96];
#pragma unroll
            for (int j = 0; j < 4; ++j) {
                unsigned long long hk2 = pack2s(__shfl_sync(0xffffffffu, h1[j], k));
                a2[j][0] = fma2(hk2, w0, a2[j][0]);
                a2[j][1] = fma2(hk2, w1, a2[j][1]);
                a2[j][2] = fma2(hk2, w2, a2[j][2]);
                a2[j][3] = fma2(hk2, w3, a2[j][3]);
            }
        }
        float acc[4];
#pragma unroll
        for (int j = 0; j < 4; ++j) {
            float s = 0.f;
#pragma unroll
            for (int p = 0; p < 4; ++p) {
                float2 av = ull2f(a2[j][p]);
                int j1 = p * 64 + lane, j2 = j1 + 32;
                s += tanh_approx(av.x + sb1[j1]) * sW2[j1];
                s += tanh_approx(av.y + sb1[j2]) * sW2[j2];
            }
            acc[j] = s;
        }
        float accA = acc[0] + acc[2];  // r=0 rows of this group
        float accB = acc[1] + acc[3];  // r=1 rows
#pragma unroll
        for (int off2 = 16; off2 > 0; off2 >>= 1) {
            accA += __shfl_down_sync(0xffffffffu, accA, off2);
            accB += __shfl_down_sync(0xffffffffu, accB, off2);
        }
        if (lane == 0) {
            int binb = (row / NR) * RR;
            atomicAdd(&sbins[binb], accA);
            atomicAdd(&sbins[binb + 1], accB);
        }
    }
    __syncthreads();
    if (tid < TT * RR) atomicAdd(&ssum[tid], sbins[tid]);
}

__global__ void beta_kernel(const float* __restrict__ ssum, float* __restrict__ beta) {
    int t = threadIdx.x;
    if (t < TT) {
        float s0 = ssum[t * RR + 0] * (1.0f / NN);
        float s1 = ssum[t * RR + 1] * (1.0f / NN);
        float m = fmaxf(s0, s1);
        float e0 = expf(s0 - m), e1 = expf(s1 - m);
        float inv = 1.f / (e0 + e1);
        beta[t * RR + 0] = e0 * inv;
        beta[t * RR + 1] = e1 * inv;
    }
}

__global__ void inter_kernel(const float* __restrict__ intra, const float* __restrict__ beta,
                             float* __restrict__ inter) {
    int idx = blockIdx.x * blockDim.x + threadIdx.x;
    if (idx >= TT * NN * CC) return;
    int t = idx / (NN * CC);
    size_t nbase = (size_t)(idx / CC) * RR * CC + (idx & 63);
    inter[idx] = beta[t * RR] * intra[nbase] + beta[t * RR + 1] * intra[nbase + CC];
}

// ----------------- LSTM pointwise -----------------
__global__ void lstm_point_kernel(const float* __restrict__ gates, float* __restrict__ lh,
                                  float* __restrict__ lc, float* __restrict__ feats, int t) {
    int idx = blockIdx.x * blockDim.x + threadIdx.x;
    if (idx >= NN * CC) return;
    int n = idx >> 6, c = idx & 63;
    const float* g = gates + (size_t)n * HC;
    float gi = g[c], gf = g[64 + c], gg = g[128 + c], go = g[192 + c];
    float cc = sigmoidf_(gf) * lc[idx] + sigmoidf_(gi) * tanhf(gg);
    lc[idx] = cc;
    float hh = sigmoidf_(go) * tanhf(cc);
    lh[idx] = hh;
    feats[((size_t)n * TT + t) * CC + c] = hh;
}

// ----------------- temporal multi-head attention: warp per node (fma2 projections) --------
__global__ __launch_bounds__(256) void attn_kernel(
    const float* __restrict__ feats, const float* __restrict__ pos,
    const float* __restrict__ Wq, const float* __restrict__ Wk, const float* __restrict__ Wv,
    float* __restrict__ out) {
    extern __shared__ float sm[];
    float* sWq = sm;
    float* sWk = sm + 4096;
    float* sWv = sm + 8192;
    float* spos = sm + 12288;
    float* wb = sm + 12544;
    int tid = threadIdx.x;
    for (int i = tid; i < 4096; i += 256) {
        sWq[i] = Wq[i]; sWk[i] = Wk[i]; sWv[i] = Wv[i];
    }
    if (tid < 256) spos[tid] = pos[tid];
    __syncthreads();
    int wid = tid >> 5, lane = tid & 31;
    int n = blockIdx.x * 8 + wid;
    if (n >= NN) return;
    float* ti = wb + wid * 1088;
    float* q = ti + 256;
    float* k_ = q + 256;
    float* v = k_ + 256;
    float* a = v + 256;
#pragma unroll
    for (int m = 0; m < 8; ++m) {
        int o = m * 32 + lane;
        ti[o] = feats[(size_t)n * 256 + o] + spos[o];
    }
    __syncwarp();
    // projections: lane owns channel pair (2*lane, 2*lane+1) for all 4 timesteps
    {
        const unsigned long long* wq64 = reinterpret_cast<const unsigned long long*>(sWq);
        const unsigned long long* wk64 = reinterpret_cast<const unsigned long long*>(sWk);
        const unsigned long long* wv64 = reinterpret_cast<const unsigned long long*>(sWv);
        unsigned long long q2[4] = {}, k2[4] = {}, v2[4] = {};
#pragma unroll 4
        for (int k = 0; k < 64; ++k) {
            unsigned long long wq = wq64[k * 32 + lane];
            unsigned long long wk = wk64[k * 32 + lane];
            unsigned long long wv = wv64[k * 32 + lane];
#pragma unroll
            for (int t = 0; t < 4; ++t) {
                unsigned long long tv = pack2s(ti[t * 64 + k]);
                q2[t] = fma2(tv, wq, q2[t]);
                k2[t] = fma2(tv, wk, k2[t]);
                v2[t] = fma2(tv, wv, v2[t]);
            }
        }
#pragma unroll
        for (int t = 0; t < 4; ++t) {
            reinterpret_cast<float2*>(q)[t * 32 + lane] = ull2f(q2[t]);
            reinterpret_cast<float2*>(k_)[t * 32 + lane] = ull2f(k2[t]);
            reinterpret_cast<float2*>(v)[t * 32 + lane] = ull2f(v2[t]);
        }
    }
    __syncwarp();
    if (lane < 16) {
        int h = lane >> 2, tq = lane & 3;
        float sc[4];
        for (int tk = 0; tk <= tq; ++tk) {
            float s = 0.f;
#pragma unroll
            for (int ch = 0; ch < 16; ++ch)
                s += q[tq * 64 + h * 16 + ch] * k_[tk * 64 + h * 16 + ch];
            sc[tk] = s * 0.5f;
        }
        float mx = sc[0];
        for (int tk = 1; tk <= tq; ++tk) mx = fmaxf(mx, sc[tk]);
        float sum = 0.f;
        for (int tk = 0; tk <= tq; ++tk) { sc[tk] = __expf(sc[tk] - mx); sum += sc[tk]; }
        float inv = 1.f / sum;
        for (int tk = 0; tk < 4; ++tk)
            a[h * 16 + tq * 4 + tk] = (tk <= tq) ? sc[tk] * inv : 0.f;
    }
    __syncwarp();
    // output: lane owns channel pair (2*lane, 2*lane+1); both in same head (h = lane/8)
    {
        int h = lane >> 3;
        const unsigned long long* v64 = reinterpret_cast<const unsigned long long*>(v);
#pragma unroll
        for (int tq = 0; tq < 4; ++tq) {
            unsigned long long acc = 0ull;
#pragma unroll
            for (int tk = 0; tk < 4; ++tk)
                acc = fma2(pack2s(a[h * 16 + tq * 4 + tk]), v64[tk * 32 + lane], acc);
            reinterpret_cast<float2*>(out + (size_t)n * 256 + tq * 64)[lane] = ull2f(acc);
        }
    }
}

// ----------------- host launch -----------------
template <typename T>
static T* symaddr(const void* sym) {
    void* p = nullptr;
    cudaGetSymbolAddress(&p, sym);
    return (T*)p;
}

extern "C" void kernel_launch(void* const* d_in, const int* in_sizes, int n_in,
                              void* d_out, int out_size) {
    const float* x = (const float*)d_in[0];
    const int* ei = (const int*)d_in[1];
    const float* W_src = (const float*)d_in[2];
    const float* W_dst = (const float*)d_in[3];
    const float* att_src = (const float*)d_in[4];
    const float* att_dst = (const float*)d_in[5];
    const float* ra_W1 = (const float*)d_in[6];
    const float* ra_b1 = (const float*)d_in[7];
    const float* ra_W2 = (const float*)d_in[8];
    const float* Wih = (const float*)d_in[9];
    const float* Whh = (const float*)d_in[10];
    const float* bih = (const float*)d_in[11];
    const float* bhh = (const float*)d_in[12];
    const float* pos = (const float*)d_in[13];
    const float* Wq = (const float*)d_in[14];
    const float* Wk = (const float*)d_in[15];
    const float* Wv = (const float*)d_in[16];
    float* out = (float*)d_out;

    float* agg = symaddr<float>(g_agg);
    float* als = symaddr<float>(g_als);
    float* ald = symaddr<float>(g_ald);
    float* intra = symaddr<float>(g_intra);
    float* ssum = symaddr<float>(g_ssum);
    float* beta = symaddr<float>(g_beta);
    float* inter = symaddr<float>(g_inter);
    float* xg = symaddr<float>(g_xg);
    float* gates = symaddr<float>(g_gates);
    float* lh = symaddr<float>(g_lh);
    float* lc = symaddr<float>(g_lc);
    float* feats = symaddr<float>(g_feats);
    float* WihT = symaddr<float>(g_WihT);
    float* WhhT = symaddr<float>(g_WhhT);
    float* biassum = symaddr<float>(g_biassum);
    float* folds = symaddr<float>(g_folds);
    float* foldd = symaddr<float>(g_foldd);
    float* Bstack = symaddr<float>(g_Bstack);
    int* cnt = symaddr<int>(g_cnt);
    int* off = symaddr<int>(g_off);
    int* posb = symaddr<int>(g_pos);
    int* sorted = symaddr<int>(g_sorted);

    const int REL_SMEM = (16384 + 256 + 256 + 8) * 4;
    const int ATT_SMEM = (12544 + 8 * 1088) * 4;
    cudaFuncSetAttribute(relation_kernel, cudaFuncAttributeMaxDynamicSharedMemorySize, REL_SMEM);
    cudaFuncSetAttribute(attn_kernel, cudaFuncAttributeMaxDynamicSharedMemorySize, ATT_SMEM);

    // ---- prep
    fold_att_kernel<<<2, 256>>>(W_src, W_dst, att_src, att_dst, folds, foldd);
    transpose_kernel<<<64, 256>>>(Wih, WihT, HC, DD);
    transpose_kernel<<<64, 256>>>(Whh, WhhT, HC, DD);
    bias_sum_kernel<<<1, 256>>>(bih, bhh, biassum);
    bstack_kernel<<<128, 256>>>(W_src, Bstack);

    // ---- CSR build (all z)
    cudaMemsetAsync(cnt, 0, (size_t)ZZ * NN * sizeof(int), 0);
    hist_kernel<<<(ZZ * EE) / 256, 256>>>(ei, cnt);
    scan_kernel<<<ZZ, 1024>>>(cnt, off, posb);
    scatter_kernel<<<(ZZ * EE) / 256, 256>>>(ei, posb, sorted);

    // ---- attention coefficients + gather (all z)
    als_all_kernel<<<(ZZ * NN * HH) / 256, 256>>>(x, folds, foldd, als, ald);
    gather_kernel<<<dim3(NN / 8, ZZ), 256>>>(off, sorted, x, als, ald, agg);

    // ---- batched intra GEMM
    gemm_intra<<<dim3((NN + 63) / 64, ZZ), 256>>>(agg, Bstack, intra);

    // ---- relation aggregation
    cudaMemsetAsync(ssum, 0, TT * RR * sizeof(float), 0);
    relation_kernel<<<444, 256, REL_SMEM>>>(intra, ra_W1, ra_b1, ra_W2, ssum);
    beta_kernel<<<1, 32>>>(ssum, beta);
    inter_kernel<<<(TT * NN * CC + 255) / 256, 256>>>(intra, beta, inter);

    // ---- LSTM
    gemm_k64<<<dim3(HC / 64, (TT * NN + 63) / 64), 256>>>(inter, WihT, xg, TT * NN, HC,
                                                          nullptr, biassum);
    cudaMemsetAsync(lh, 0, (size_t)NN * CC * sizeof(float), 0);
    cudaMemsetAsync(lc, 0, (size_t)NN * CC * sizeof(float), 0);
    for (int t = 0; t < TT; ++t) {
        gemm_k64<<<dim3(HC / 64, (NN + 63) / 64), 256>>>(
            lh, WhhT, gates, NN, HC, xg + (size_t)t * NN * HC, nullptr);
        lstm_point_kernel<<<(NN * CC + 255) / 256, 256>>>(gates, lh, lc, feats, t);
    }

    // ---- temporal attention
    attn_kernel<<<(NN + 7) / 8, 256, ATT_SMEM>>>(feats, pos, Wq, Wk, Wv, out);
}